// round 11
// baseline (speedup 1.0000x reference)
#include <cuda_runtime.h>
#include <cuda_bf16.h>

// Masked trapezoid loss as weighted dot product:
//   S_b = sum_{k=0}^{idx} g_w[k]*d[k] + corr(idx),  d = y_pred - y_true
//   g_w[k] = 0.5*(x[min(k+1,n-1)] - x[max(k-1,0)])
//   corr = -g_w[0]*d[0]                   if idx == 0
//        = -0.5*(x[idx+1]-x[idx])*d[idx]  if 1 <= idx <= n-2
//        = 0                              if idx == n-1
// Output: mean_b (S_b)^2 (one fp32 scalar).
//
// Structure: warp-per-row, predication-free hot loop (vectors 0..nfull-1 are
// fully inside the mask; lane 0 handles the <=3 remainder elements and the
// endpoint correction). Per-row results land in g_S[row] (no atomics, no
// reset ordering); a single-block fp64 reduce produces the mean.

#define NMAX 8192
#define BMAX 65536

__device__ float g_w[NMAX];
__device__ float g_S[BMAX];

__global__ void weights_kernel(const float* __restrict__ x, int n) {
    int k = blockIdx.x * blockDim.x + threadIdx.x;
    if (k >= n) return;
    float lo = (k == 0)     ? x[0]     : x[k - 1];
    float hi = (k == n - 1) ? x[n - 1] : x[k + 1];
    g_w[k] = 0.5f * (hi - lo);
}

__global__ __launch_bounds__(256) void row_kernel(
    const float* __restrict__ yp, const float* __restrict__ yt,
    const float* __restrict__ x,  const int* __restrict__ fidx,
    int n, int B)
{
    int row  = blockIdx.x * 8 + (threadIdx.x >> 5);
    if (row >= B) return;
    int lane = threadIdx.x & 31;

    int idx = fidx[row];
    idx = idx < 0 ? 0 : (idx > n - 1 ? n - 1 : idx);   // clamp as reference

    const float* yprow = yp + (size_t)row * (size_t)n;
    const float* ytrow = yt + (size_t)row * (size_t)n;
    const float4* p4 = (const float4*)yprow;
    const float4* t4 = (const float4*)ytrow;
    const float4* w4 = (const float4*)g_w;

    int nfull = (idx + 1) >> 2;     // vectors fully inside the mask
    float acc = 0.0f;

    int v = lane;
    // 4-deep batched main loop: 12 LDG.128 front-batched per iteration.
    for (; v + 96 < nfull; v += 128) {
        float4 pa = __ldcs(p4 + v),      pb = __ldcs(p4 + v + 32);
        float4 pc = __ldcs(p4 + v + 64), pd = __ldcs(p4 + v + 96);
        float4 ta = __ldcs(t4 + v),      tb = __ldcs(t4 + v + 32);
        float4 tc = __ldcs(t4 + v + 64), td = __ldcs(t4 + v + 96);
        float4 wa = w4[v],      wb = w4[v + 32];
        float4 wc = w4[v + 64], wd = w4[v + 96];
        acc = fmaf(wa.x, pa.x - ta.x, acc);
        acc = fmaf(wa.y, pa.y - ta.y, acc);
        acc = fmaf(wa.z, pa.z - ta.z, acc);
        acc = fmaf(wa.w, pa.w - ta.w, acc);
        acc = fmaf(wb.x, pb.x - tb.x, acc);
        acc = fmaf(wb.y, pb.y - tb.y, acc);
        acc = fmaf(wb.z, pb.z - tb.z, acc);
        acc = fmaf(wb.w, pb.w - tb.w, acc);
        acc = fmaf(wc.x, pc.x - tc.x, acc);
        acc = fmaf(wc.y, pc.y - tc.y, acc);
        acc = fmaf(wc.z, pc.z - tc.z, acc);
        acc = fmaf(wc.w, pc.w - tc.w, acc);
        acc = fmaf(wd.x, pd.x - td.x, acc);
        acc = fmaf(wd.y, pd.y - td.y, acc);
        acc = fmaf(wd.z, pd.z - td.z, acc);
        acc = fmaf(wd.w, pd.w - td.w, acc);
    }
    // remaining full vectors (still no per-element masking)
    for (; v < nfull; v += 32) {
        float4 p = __ldcs(p4 + v);
        float4 t = __ldcs(t4 + v);
        float4 w = w4[v];
        acc = fmaf(w.x, p.x - t.x, acc);
        acc = fmaf(w.y, p.y - t.y, acc);
        acc = fmaf(w.z, p.z - t.z, acc);
        acc = fmaf(w.w, p.w - t.w, acc);
    }

    if (lane == 0) {
        // partial last vector: elements 4*nfull .. idx  (<=3 of them)
        int k0 = nfull << 2;
        for (int k = k0; k <= idx; k++)
            acc = fmaf(g_w[k], yprow[k] - ytrow[k], acc);
        // endpoint correction
        float dend = yprow[idx] - ytrow[idx];
        if (idx == 0)          acc -= g_w[0] * dend;
        else if (idx < n - 1)  acc -= 0.5f * (x[idx + 1] - x[idx]) * dend;
    }

    // warp tree reduce
    #pragma unroll
    for (int o = 16; o > 0; o >>= 1)
        acc += __shfl_xor_sync(0xffffffffu, acc, o);

    if (lane == 0)
        g_S[row] = acc;
}

__global__ __launch_bounds__(256) void final_kernel(
    float* __restrict__ out, int B, float invB)
{
    __shared__ double sm[8];
    int t = threadIdx.x;

    double s = 0.0;
    for (int r = t; r < B; r += 256) {
        double v = (double)g_S[r];
        s += v * v;
    }
    #pragma unroll
    for (int o = 16; o > 0; o >>= 1)
        s += __shfl_xor_sync(0xffffffffu, s, o);
    if ((t & 31) == 0) sm[t >> 5] = s;
    __syncthreads();
    if (t == 0) {
        double tot = 0.0;
        #pragma unroll
        for (int w = 0; w < 8; w++) tot += sm[w];
        out[0] = (float)(tot * (double)invB);
    }
}

extern "C" void kernel_launch(void* const* d_in, const int* in_sizes, int n_in,
                              void* d_out, int out_size) {
    // metadata order: y_pred [B*N] f32, y_true [B*N] f32, x_values [N] f32,
    //                 fracture_idx [B] i32
    const float* yp   = (const float*)d_in[0];
    const float* yt   = (const float*)d_in[1];
    const float* x    = (const float*)d_in[2];
    const int*   fidx = (const int*)d_in[3];
    int n = in_sizes[2];
    int B = in_sizes[3];

    weights_kernel<<<(n + 255) / 256, 256>>>(x, n);
    row_kernel<<<(B + 7) / 8, 256>>>(yp, yt, x, fidx, n, B);
    final_kernel<<<1, 256>>>((float*)d_out, B, 1.0f / (float)B);
}